// round 8
// baseline (speedup 1.0000x reference)
#include <cuda_runtime.h>
#include <cuda_bf16.h>
#include <math.h>
#include <stdint.h>

#define N_ROWS 65536
#define DD 512
#define EE 256
#define TT 128
#define KK 5
#define KTOT 896

#define BM 64
#define BN 512
#define BK 32
#define NCH (KTOT / BK)     // 28
#define APADB 80            // bytes per k-row in smem tiles
#define XSTRIDE 520         // xbuf row stride in bf16 elems

#define SM_A0 0u
#define SM_A1 5120u
#define SM_B0 10240u
#define SM_B1 51200u
#define SMEM_TOTAL 92160u

// ---------------- device scratch ----------------
__device__ __align__(16) __nv_bfloat16 g_Wq_bf16[DD * KTOT];        // [512][896]
__device__ __align__(16) __nv_bfloat16 g_x[(size_t)N_ROWS * DD];    // pre-LN query + bias (bf16)

__device__ __forceinline__ float clipf(float x, float lo, float hi) {
    return fminf(fmaxf(x, lo), hi);
}
__device__ __forceinline__ uint32_t sptr(const void* p) {
    return (uint32_t)__cvta_generic_to_shared(p);
}

__global__ void convert_wq(const float* __restrict__ Wq) {
    int i = blockIdx.x * blockDim.x + threadIdx.x;
    if (i < DD * KTOT) g_Wq_bf16[i] = __float2bfloat16(Wq[i]);
}

__device__ __forceinline__ void mma16816(float c[4], uint32_t a0, uint32_t a1,
                                         uint32_t a2, uint32_t a3,
                                         uint32_t b0, uint32_t b1) {
    asm volatile(
        "mma.sync.aligned.m16n8k16.row.col.f32.bf16.bf16.f32 "
        "{%0,%1,%2,%3}, {%4,%5,%6,%7}, {%8,%9}, {%0,%1,%2,%3};\n"
        : "+f"(c[0]), "+f"(c[1]), "+f"(c[2]), "+f"(c[3])
        : "r"(a0), "r"(a1), "r"(a2), "r"(a3), "r"(b0), "r"(b1));
}
__device__ __forceinline__ void ldsm4(uint32_t& r0, uint32_t& r1, uint32_t& r2,
                                      uint32_t& r3, uint32_t addr) {
    asm volatile("ldmatrix.sync.aligned.m8n8.x4.shared.b16 {%0,%1,%2,%3}, [%4];"
                 : "=r"(r0), "=r"(r1), "=r"(r2), "=r"(r3) : "r"(addr));
}

// ---------------------------------------------------------------------------
// Kernel 1: GEMM only. 512 threads = 16 warps (2 x 8), warp tile 32x64.
// x (bf16, +bias) -> g_x via smem staging (coalesced).
// ---------------------------------------------------------------------------
__global__ __launch_bounds__(512, 1) void qproj_gemm(
    const float* __restrict__ raw,
    const float* __restrict__ edge,
    const float* __restrict__ timeenc,
    const float* __restrict__ bq)
{
    extern __shared__ char smem[];
    const uint32_t sb = sptr(smem);
    const int tid  = threadIdx.x;
    const int lane = tid & 31;
    const int wid  = tid >> 5;
    const int wm   = wid >> 3;      // 0..1
    const int wn   = wid & 7;       // 0..7
    const int n0   = blockIdx.x * BM;

    float acc[2][8][4];
    #pragma unroll
    for (int mt = 0; mt < 2; mt++)
        #pragma unroll
        for (int nt = 0; nt < 8; nt++)
            #pragma unroll
            for (int j = 0; j < 4; j++) acc[mt][nt][j] = 0.f;

    float4 areg;

    auto ldgA = [&](int c) {
        const int kt = c * BK;
        const float* src; int stride;
        if (kt < DD)            { src = raw     + (size_t)n0 * DD + kt;             stride = DD; }
        else if (kt < DD + EE)  { src = edge    + (size_t)n0 * EE + (kt - DD);      stride = EE; }
        else                    { src = timeenc + (size_t)n0 * TT + (kt - DD - EE); stride = TT; }
        int m  = tid >> 3;
        int kk = (tid & 7) * 4;
        areg = *(const float4*)(src + (size_t)m * stride + kk);
    };
    auto stsA = [&](int b) {
        const uint32_t Ab = b ? SM_A1 : SM_A0;
        int m  = tid >> 3;
        int kk = (tid & 7) * 4;
        float4 v = areg;
        v.x = clipf(v.x, -50.f, 50.f); v.y = clipf(v.y, -50.f, 50.f);
        v.z = clipf(v.z, -50.f, 50.f); v.w = clipf(v.w, -50.f, 50.f);
        __nv_bfloat162 lo = __float22bfloat162_rn(make_float2(v.x, v.y));
        __nv_bfloat162 hi = __float22bfloat162_rn(make_float2(v.z, v.w));
        uint2 pk;
        pk.x = *(uint32_t*)&lo; pk.y = *(uint32_t*)&hi;
        *(uint2*)(smem + Ab + m * APADB + kk * 2) = pk;
    };
    auto cpB = [&](int c, int b) {
        const int kt = c * BK;
        const uint32_t Bb = sb + (b ? SM_B1 : SM_B0);
        #pragma unroll
        for (int i = 0; i < 4; i++) {
            int id = tid + i * 512;            // 2048 x 16B
            int r  = id >> 2;
            int qt = id & 3;
            const __nv_bfloat16* src = g_Wq_bf16 + (size_t)r * KTOT + kt + qt * 8;
            uint32_t dst = Bb + r * APADB + qt * 16;
            asm volatile("cp.async.ca.shared.global [%0], [%1], 16;\n" :: "r"(dst), "l"(src));
        }
    };
    auto compute = [&](int b) {
        const uint32_t Ab = sb + (b ? SM_A1 : SM_A0);
        const uint32_t Bb = sb + (b ? SM_B1 : SM_B0);
        #pragma unroll
        for (int ks = 0; ks < 2; ks++) {
            uint32_t a[2][4], bf[8][2];
            #pragma unroll
            for (int mt = 0; mt < 2; mt++) {
                uint32_t addr = Ab + (uint32_t)(wm * 32 + mt * 16 + (lane & 15)) * APADB
                              + (uint32_t)(ks * 16 + ((lane >> 4) << 3)) * 2;
                ldsm4(a[mt][0], a[mt][1], a[mt][2], a[mt][3], addr);
            }
            #pragma unroll
            for (int pr = 0; pr < 4; pr++) {
                int nb = wn * 64 + pr * 16;
                uint32_t addr = Bb + (uint32_t)(nb + ((lane >> 4) << 3) + (lane & 7)) * APADB
                              + (uint32_t)(ks * 16 + ((lane >> 3) & 1) * 8) * 2;
                ldsm4(bf[2*pr][0], bf[2*pr][1], bf[2*pr+1][0], bf[2*pr+1][1], addr);
            }
            #pragma unroll
            for (int mt = 0; mt < 2; mt++)
                #pragma unroll
                for (int nt = 0; nt < 8; nt++)
                    mma16816(acc[mt][nt], a[mt][0], a[mt][1], a[mt][2], a[mt][3],
                             bf[nt][0], bf[nt][1]);
        }
    };

    ldgA(0);
    cpB(0, 0);
    asm volatile("cp.async.commit_group;\n" ::: "memory");
    stsA(0);
    asm volatile("cp.async.wait_group 0;\n" ::: "memory");
    __syncthreads();

    int buf = 0;
    for (int c = 0; c < NCH; c++) {
        if (c < NCH - 1) {
            ldgA(c + 1);
            cpB(c + 1, buf ^ 1);
            asm volatile("cp.async.commit_group;\n" ::: "memory");
        }
        compute(buf);
        if (c < NCH - 1) stsA(buf ^ 1);
        asm volatile("cp.async.wait_group 0;\n" ::: "memory");
        __syncthreads();
        buf ^= 1;
    }

    // ---- epilogue: fragments (+bias) -> smem bf16 -> g_x (coalesced) ----
    __nv_bfloat16* xb = (__nv_bfloat16*)smem;
    #pragma unroll
    for (int mt = 0; mt < 2; mt++) {
        #pragma unroll
        for (int nt = 0; nt < 8; nt++) {
            int row = wm * 32 + mt * 16 + (lane >> 2);
            int col = wn * 64 + nt * 8 + (lane & 3) * 2;
            float b0 = __ldg(bq + col), b1 = __ldg(bq + col + 1);
            __nv_bfloat162 v0 = __float22bfloat162_rn(
                make_float2(acc[mt][nt][0] + b0, acc[mt][nt][1] + b1));
            __nv_bfloat162 v1 = __float22bfloat162_rn(
                make_float2(acc[mt][nt][2] + b0, acc[mt][nt][3] + b1));
            *(__nv_bfloat162*)&xb[row * XSTRIDE + col]       = v0;
            *(__nv_bfloat162*)&xb[(row + 8) * XSTRIDE + col] = v1;
        }
    }
    __syncthreads();
    #pragma unroll
    for (int i = 0; i < 8; i++) {
        int idx = tid + i * 512;            // 4096 uint4 = 64 rows x 64
        int row = idx >> 6;
        int q   = idx & 63;
        uint4 v = *(const uint4*)&xb[row * XSTRIDE + q * 8];
        *(uint4*)(g_x + (size_t)(n0 + row) * DD + q * 8) = v;
    }
}

// ---------------------------------------------------------------------------
// Kernel 2: per-row LN/tanh + attention + gate + residual + LN.
// One 128-thread block per row (high occupancy); single proto pass in regs.
// ---------------------------------------------------------------------------
template <int M>
__device__ __forceinline__ void block_reduce(float* v, float (*red)[16], int tid) {
    int lane = tid & 31, w = tid >> 5;
    #pragma unroll
    for (int off = 16; off > 0; off >>= 1)
        #pragma unroll
        for (int m = 0; m < M; m++)
            v[m] += __shfl_down_sync(0xffffffffu, v[m], off);
    if (lane == 0)
        #pragma unroll
        for (int m = 0; m < M; m++) red[w][m] = v[m];
    __syncthreads();
    #pragma unroll
    for (int m = 0; m < M; m++)
        v[m] = red[0][m] + red[1][m] + red[2][m] + red[3][m];
    __syncthreads();
}

__global__ __launch_bounds__(128) void row_kernel(
    const float* __restrict__ raw,
    const float* __restrict__ timeenc,
    const float* __restrict__ proto,
    const float* __restrict__ Wg,
    const float* __restrict__ bg,
    const float* __restrict__ gamma,
    const float* __restrict__ beta,
    const float* __restrict__ temperature,
    float* __restrict__ out)
{
    const int n = blockIdx.x;
    const int tid = threadIdx.x;
    const int d0 = tid * 4;
    __shared__ float red[4][16];

    float xq[4], r[4], p[KK][4], gm[4], bt[4];
    {
        uint2 u2 = *(const uint2*)(g_x + (size_t)n * DD + d0);
        __nv_bfloat162 p0 = *(__nv_bfloat162*)&u2.x;
        __nv_bfloat162 p1 = *(__nv_bfloat162*)&u2.y;
        float2 f0 = __bfloat1622float2(p0);
        float2 f1 = __bfloat1622float2(p1);
        xq[0] = f0.x; xq[1] = f0.y; xq[2] = f1.x; xq[3] = f1.y;

        float4 rv = *(const float4*)(raw + (size_t)n * DD + d0);
        r[0] = clipf(rv.x, -50.f, 50.f); r[1] = clipf(rv.y, -50.f, 50.f);
        r[2] = clipf(rv.z, -50.f, 50.f); r[3] = clipf(rv.w, -50.f, 50.f);
        float4 gv = *(const float4*)(gamma + d0);
        gm[0] = gv.x; gm[1] = gv.y; gm[2] = gv.z; gm[3] = gv.w;
        float4 bv = *(const float4*)(beta + d0);
        bt[0] = bv.x; bt[1] = bv.y; bt[2] = bv.z; bt[3] = bv.w;
    }
    float tv = timeenc[(size_t)n * TT + tid];
    #pragma unroll
    for (int k = 0; k < KK; k++) {
        float4 pv = *(const float4*)(proto + ((size_t)n * KK + k) * DD + d0);
        p[k][0] = pv.x; p[k][1] = pv.y; p[k][2] = pv.z; p[k][3] = pv.w;
    }

    // ---- query LN + tanh ----
    float st2[2] = {0.f, 0.f};
    #pragma unroll
    for (int j = 0; j < 4; j++) { st2[0] += xq[j]; st2[1] += xq[j] * xq[j]; }
    block_reduce<2>(st2, red, tid);
    {
        float mu   = st2[0] * (1.f / DD);
        float var  = st2[1] * (1.f / DD) - mu * mu;
        float rstd = rsqrtf(var + 1e-6f);
        #pragma unroll
        for (int j = 0; j < 4; j++)
            xq[j] = tanhf((xq[j] - mu) * rstd * gm[j] + bt[j]);   // xq is now q
    }

    // ---- norms + dots ----
    float part[11];
    {
        float qss = 0.f;
        #pragma unroll
        for (int j = 0; j < 4; j++) qss += xq[j] * xq[j];
        part[0] = qss;
        #pragma unroll
        for (int k = 0; k < KK; k++) {
            float pss = 0.f, pdot = 0.f;
            #pragma unroll
            for (int j = 0; j < 4; j++) {
                float ps = clipf(p[k][j], -20.f, 20.f);
                pss  = fmaf(ps, ps, pss);
                pdot = fmaf(ps, xq[j], pdot);
            }
            part[1 + k] = pss;
            part[6 + k] = pdot;
        }
    }
    block_reduce<11>(part, red, tid);

    float qn = fmaxf(sqrtf(part[0]), 1e-6f);
    float temp = clipf(temperature[0], 0.5f, 5.0f) + 1e-4f;
    float sim[KK], mx = -1e30f;
    #pragma unroll
    for (int k = 0; k < KK; k++) {
        float s = part[6 + k] / (qn * fmaxf(sqrtf(part[1 + k]), 1e-6f));
        s = clipf(s, -15.f, 15.f) / temp;
        sim[k] = s; mx = fmaxf(mx, s);
    }
    float denom = 0.f, attn[KK];
    #pragma unroll
    for (int k = 0; k < KK; k++) { attn[k] = expf(sim[k] - mx); denom += attn[k]; }
    float inv = 1.f / denom;
    #pragma unroll
    for (int k = 0; k < KK; k++) attn[k] = clipf(attn[k] * inv, 0.f, 1.f);

    float cand[4];
    #pragma unroll
    for (int j = 0; j < 4; j++) {
        float cc = attn[0] * p[0][j];
        #pragma unroll
        for (int k = 1; k < KK; k++) cc = fmaf(attn[k], p[k][j], cc);
        cand[j] = clipf(cc, -5.f, 5.f);
    }

    // ---- gate ----
    float gp[1] = {0.f};
    {
        float4 w0 = *(const float4*)(Wg + d0);
        float4 w1 = *(const float4*)(Wg + DD + d0);
        const float* wr0 = (const float*)&w0;
        const float* wr1 = (const float*)&w1;
        #pragma unroll
        for (int j = 0; j < 4; j++) {
            gp[0] += wr0[j] * clipf(r[j],    -30.f, 30.f);
            gp[0] += wr1[j] * clipf(cand[j], -30.f, 30.f);
        }
        gp[0] += Wg[2 * DD + tid] * clipf(tv, -30.f, 30.f);
    }
    block_reduce<1>(gp, red, tid);
    float gl = clipf(gp[0] + bg[0], -10.f, 10.f);
    float g = 1.f / (1.f + expf(-gl));

    // ---- residual + final LN ----
    float u[4], st[2] = {0.f, 0.f};
    #pragma unroll
    for (int j = 0; j < 4; j++) {
        u[j] = 0.8f * r[j] + 0.2f * ((1.f - g) * r[j] + g * cand[j]);
        st[0] += u[j];
        st[1] += u[j] * u[j];
    }
    block_reduce<2>(st, red, tid);
    float mu   = st[0] * (1.f / DD);
    float var  = st[1] * (1.f / DD) - mu * mu;
    float rstd = rsqrtf(var + 1e-6f);

    float4 o;
    float* op = (float*)&o;
    #pragma unroll
    for (int j = 0; j < 4; j++)
        op[j] = clipf((u[j] - mu) * rstd * gm[j] + bt[j], -10.f, 10.f);
    *(float4*)(out + (size_t)n * DD + d0) = o;
}

// ---------------------------------------------------------------------------
extern "C" void kernel_launch(void* const* d_in, const int* in_sizes, int n_in,
                              void* d_out, int out_size) {
    const float* raw   = (const float*)d_in[0];
    // d_in[1] = node_features (unused by reference)
    const float* edge  = (const float*)d_in[2];
    const float* timee = (const float*)d_in[3];
    const float* proto = (const float*)d_in[4];
    const float* Wq    = (const float*)d_in[5];
    const float* bq    = (const float*)d_in[6];
    const float* Wg    = (const float*)d_in[7];
    const float* bg    = (const float*)d_in[8];
    const float* gamma = (const float*)d_in[9];
    const float* beta  = (const float*)d_in[10];
    const float* temp  = (const float*)d_in[11];
    float* out = (float*)d_out;

    cudaFuncSetAttribute(qproj_gemm, cudaFuncAttributeMaxDynamicSharedMemorySize, SMEM_TOTAL);

    convert_wq<<<(DD * KTOT + 255) / 256, 256>>>(Wq);
    qproj_gemm<<<N_ROWS / BM, 512, SMEM_TOTAL>>>(raw, edge, timee, bq);
    row_kernel<<<N_ROWS, 128>>>(raw, timee, proto, Wg, bg, gamma, beta, temp, out);
}

// round 9
// speedup vs baseline: 1.0714x; 1.0714x over previous
#include <cuda_runtime.h>
#include <cuda_bf16.h>
#include <math.h>
#include <stdint.h>

#define N_ROWS 65536
#define DD 512
#define EE 256
#define TT 128
#define KK 5
#define KTOT 896

#define BM 64
#define BN 512
#define BK 32
#define NCH (KTOT / BK)     // 28
#define APADB 80            // bytes per k-row in smem tiles
#define XSTRIDE 520         // xbuf row stride in bf16 elems

// smem: A 2 x 5120 | B 3 x 40960  (xbuf reuses [0, 66560) after mainloop)
#define SM_A0 0u
#define SM_A1 5120u
#define SM_B(s) (10240u + (uint32_t)(s) * 40960u)
#define SMEM_TOTAL 133120u

// ---------------- device scratch ----------------
__device__ __align__(16) __nv_bfloat16 g_Wq_bf16[DD * KTOT];   // [512][896] K-major

__device__ __forceinline__ float clipf(float x, float lo, float hi) {
    return fminf(fmaxf(x, lo), hi);
}
__device__ __forceinline__ uint32_t sptr(const void* p) {
    return (uint32_t)__cvta_generic_to_shared(p);
}

__global__ void convert_wq(const float* __restrict__ Wq) {
    int i = blockIdx.x * blockDim.x + threadIdx.x;
    if (i < DD * KTOT) g_Wq_bf16[i] = __float2bfloat16(Wq[i]);
}

__device__ __forceinline__ void mma16816(float c[4], uint32_t a0, uint32_t a1,
                                         uint32_t a2, uint32_t a3,
                                         uint32_t b0, uint32_t b1) {
    asm volatile(
        "mma.sync.aligned.m16n8k16.row.col.f32.bf16.bf16.f32 "
        "{%0,%1,%2,%3}, {%4,%5,%6,%7}, {%8,%9}, {%0,%1,%2,%3};\n"
        : "+f"(c[0]), "+f"(c[1]), "+f"(c[2]), "+f"(c[3])
        : "r"(a0), "r"(a1), "r"(a2), "r"(a3), "r"(b0), "r"(b1));
}
__device__ __forceinline__ void ldsm4(uint32_t& r0, uint32_t& r1, uint32_t& r2,
                                      uint32_t& r3, uint32_t addr) {
    asm volatile("ldmatrix.sync.aligned.m8n8.x4.shared.b16 {%0,%1,%2,%3}, [%4];"
                 : "=r"(r0), "=r"(r1), "=r"(r2), "=r"(r3) : "r"(addr));
}

template <int M>
__device__ __forceinline__ void warp_reduce(float* v) {
    #pragma unroll
    for (int off = 16; off > 0; off >>= 1)
        #pragma unroll
        for (int m = 0; m < M; m++)
            v[m] += __shfl_xor_sync(0xffffffffu, v[m], off);
}

// ---------------------------------------------------------------------------
// Fused: 64x512x896 bf16 HMMA GEMM + LN/tanh + attention + gate + residual + LN
// 256 threads = 8 warps, warp tile 64x64 (n-split); 3-stage B pipeline.
// Row phase: 8 rows/warp, prototypes register-resident (single DRAM pass).
// ---------------------------------------------------------------------------
__global__ __launch_bounds__(256, 1) void fused_kernel(
    const float* __restrict__ raw,
    const float* __restrict__ edge,
    const float* __restrict__ timeenc,
    const float* __restrict__ proto,
    const float* __restrict__ bq,
    const float* __restrict__ Wg,
    const float* __restrict__ bg,
    const float* __restrict__ gamma,
    const float* __restrict__ beta,
    const float* __restrict__ temperature,
    float* __restrict__ out)
{
    extern __shared__ char smem[];
    const uint32_t sb = sptr(smem);
    const int tid  = threadIdx.x;
    const int lane = tid & 31;
    const int wid  = tid >> 5;
    const int n0   = blockIdx.x * BM;

    float acc[4][8][4];
    #pragma unroll
    for (int mt = 0; mt < 4; mt++)
        #pragma unroll
        for (int nt = 0; nt < 8; nt++)
            #pragma unroll
            for (int j = 0; j < 4; j++) acc[mt][nt][j] = 0.f;

    float4 areg[2];

    auto ldgA = [&](int c) {
        const int kt = c * BK;
        const float* src; int stride;
        if (kt < DD)            { src = raw     + (size_t)n0 * DD + kt;             stride = DD; }
        else if (kt < DD + EE)  { src = edge    + (size_t)n0 * EE + (kt - DD);      stride = EE; }
        else                    { src = timeenc + (size_t)n0 * TT + (kt - DD - EE); stride = TT; }
        #pragma unroll
        for (int i = 0; i < 2; i++) {
            int id = tid + i * 256;            // 512 float4s
            int m  = id >> 3;
            int kk = (id & 7) * 4;
            areg[i] = *(const float4*)(src + (size_t)m * stride + kk);
        }
    };
    auto stsA = [&](int b) {
        const uint32_t Ab = b ? SM_A1 : SM_A0;
        #pragma unroll
        for (int i = 0; i < 2; i++) {
            int id = tid + i * 256;
            int m  = id >> 3;
            int kk = (id & 7) * 4;
            float4 v = areg[i];
            v.x = clipf(v.x, -50.f, 50.f); v.y = clipf(v.y, -50.f, 50.f);
            v.z = clipf(v.z, -50.f, 50.f); v.w = clipf(v.w, -50.f, 50.f);
            __nv_bfloat162 lo = __float22bfloat162_rn(make_float2(v.x, v.y));
            __nv_bfloat162 hi = __float22bfloat162_rn(make_float2(v.z, v.w));
            uint2 pk;
            pk.x = *(uint32_t*)&lo; pk.y = *(uint32_t*)&hi;
            *(uint2*)(smem + Ab + m * APADB + kk * 2) = pk;
        }
    };
    auto cpB = [&](int c, int s) {
        const int kt = c * BK;
        const uint32_t Bb = sb + SM_B(s);
        #pragma unroll
        for (int i = 0; i < 8; i++) {
            int id = tid + i * 256;            // 2048 x 16B
            int r  = id >> 2;
            int qt = id & 3;
            const __nv_bfloat16* src = g_Wq_bf16 + (size_t)r * KTOT + kt + qt * 8;
            uint32_t dst = Bb + r * APADB + qt * 16;
            asm volatile("cp.async.ca.shared.global [%0], [%1], 16;\n" :: "r"(dst), "l"(src));
        }
    };
    auto compute = [&](int s, int ab) {
        const uint32_t Ab = sb + (ab ? SM_A1 : SM_A0);
        const uint32_t Bb = sb + SM_B(s);
        #pragma unroll
        for (int ks = 0; ks < 2; ks++) {
            uint32_t a[4][4], bf[8][2];
            #pragma unroll
            for (int mt = 0; mt < 4; mt++) {
                uint32_t addr = Ab + (uint32_t)(mt * 16 + (lane & 15)) * APADB
                              + (uint32_t)(ks * 16 + ((lane >> 4) << 3)) * 2;
                ldsm4(a[mt][0], a[mt][1], a[mt][2], a[mt][3], addr);
            }
            #pragma unroll
            for (int pr = 0; pr < 4; pr++) {
                int nb = wid * 64 + pr * 16;
                uint32_t addr = Bb + (uint32_t)(nb + ((lane >> 4) << 3) + (lane & 7)) * APADB
                              + (uint32_t)(ks * 16 + ((lane >> 3) & 1) * 8) * 2;
                ldsm4(bf[2*pr][0], bf[2*pr][1], bf[2*pr+1][0], bf[2*pr+1][1], addr);
            }
            #pragma unroll
            for (int mt = 0; mt < 4; mt++)
                #pragma unroll
                for (int nt = 0; nt < 8; nt++)
                    mma16816(acc[mt][nt], a[mt][0], a[mt][1], a[mt][2], a[mt][3],
                             bf[nt][0], bf[nt][1]);
        }
    };
    // ---- L2 prefetch of epilogue streams, spread over chunks ----
    auto prefetch_slice = [&](int c) {
        int idx = c * 256 + tid;
        const char* pf = nullptr;
        if (idx < 5120)       pf = (const char*)(proto + (size_t)n0 * KK * DD) + (size_t)idx * 128;
        else if (idx < 6144)  pf = (const char*)(raw   + (size_t)n0 * DD)      + (size_t)(idx - 5120) * 128;
        else if (idx < 6400)  pf = (const char*)(timeenc + (size_t)n0 * TT)    + (size_t)(idx - 6144) * 128;
        if (pf) asm volatile("prefetch.global.L2 [%0];" :: "l"(pf));
    };

    // ---- pipeline prologue: B groups for chunks 0,1 in flight; A chunk 0 staged ----
    cpB(0, 0);
    asm volatile("cp.async.commit_group;\n" ::: "memory");
    cpB(1, 1);
    asm volatile("cp.async.commit_group;\n" ::: "memory");
    ldgA(0);
    stsA(0);
    asm volatile("cp.async.wait_group 1;\n" ::: "memory");   // chunk 0 B ready
    __syncthreads();

    int ab = 0;
    for (int c = 0; c < NCH; c++) {
        if (c + 2 < NCH) {
            cpB(c + 2, (c + 2) % 3);
            asm volatile("cp.async.commit_group;\n" ::: "memory");
        }
        if (c + 1 < NCH) ldgA(c + 1);
        prefetch_slice(c);
        compute(c % 3, ab);
        if (c + 1 < NCH) stsA(ab ^ 1);
        if (c + 2 < NCH) {
            asm volatile("cp.async.wait_group 1;\n" ::: "memory");   // chunk c+1 B ready
        } else {
            asm volatile("cp.async.wait_group 0;\n" ::: "memory");
        }
        __syncthreads();
        ab ^= 1;
    }

    // ======================= epilogue =======================
    // 1) fragments (+bias) -> xbuf bf16 [64][XSTRIDE], reusing pipeline smem
    __nv_bfloat16* xb = (__nv_bfloat16*)smem;
    #pragma unroll
    for (int mt = 0; mt < 4; mt++) {
        #pragma unroll
        for (int nt = 0; nt < 8; nt++) {
            int row = mt * 16 + (lane >> 2);
            int col = wid * 64 + nt * 8 + (lane & 3) * 2;
            float b0 = __ldg(bq + col), b1 = __ldg(bq + col + 1);
            __nv_bfloat162 v0 = __float22bfloat162_rn(
                make_float2(acc[mt][nt][0] + b0, acc[mt][nt][1] + b1));
            __nv_bfloat162 v1 = __float22bfloat162_rn(
                make_float2(acc[mt][nt][2] + b0, acc[mt][nt][3] + b1));
            *(__nv_bfloat162*)&xb[row * XSTRIDE + col]       = v0;
            *(__nv_bfloat162*)&xb[(row + 8) * XSTRIDE + col] = v1;
        }
    }
    __syncthreads();

    // 2) row phase: warp w handles rows w*8 .. w*8+7.
    float gmv[16], btv[16], wg0[16], wg1[16], wg2[4];
    #pragma unroll
    for (int j = 0; j < 4; j++) {
        int cc = lane * 4 + j * 128;
        float4 g4 = *(const float4*)(gamma + cc);
        float4 b4 = *(const float4*)(beta + cc);
        float4 w04 = *(const float4*)(Wg + cc);
        float4 w14 = *(const float4*)(Wg + DD + cc);
        gmv[j*4+0]=g4.x; gmv[j*4+1]=g4.y; gmv[j*4+2]=g4.z; gmv[j*4+3]=g4.w;
        btv[j*4+0]=b4.x; btv[j*4+1]=b4.y; btv[j*4+2]=b4.z; btv[j*4+3]=b4.w;
        wg0[j*4+0]=w04.x; wg0[j*4+1]=w04.y; wg0[j*4+2]=w04.z; wg0[j*4+3]=w04.w;
        wg1[j*4+0]=w14.x; wg1[j*4+1]=w14.y; wg1[j*4+2]=w14.z; wg1[j*4+3]=w14.w;
    }
    {
        float4 w24 = *(const float4*)(Wg + 2 * DD + lane * 4);
        wg2[0]=w24.x; wg2[1]=w24.y; wg2[2]=w24.z; wg2[3]=w24.w;
    }
    const float bgv  = __ldg(bg);
    const float temp = clipf(__ldg(temperature), 0.5f, 5.0f) + 1e-4f;

    for (int i = 0; i < 8; i++) {
        const int lr = wid * 8 + i;
        const int n  = n0 + lr;

        // xq -> fp32
        float q[16];
        #pragma unroll
        for (int j = 0; j < 4; j++) {
            uint2 u2 = *(const uint2*)&xb[lr * XSTRIDE + lane * 4 + j * 128];
            __nv_bfloat162 p0 = *(__nv_bfloat162*)&u2.x;
            __nv_bfloat162 p1 = *(__nv_bfloat162*)&u2.y;
            float2 f0 = __bfloat1622float2(p0);
            float2 f1 = __bfloat1622float2(p1);
            q[j*4+0]=f0.x; q[j*4+1]=f0.y; q[j*4+2]=f1.x; q[j*4+3]=f1.y;
        }
        // query LN + tanh
        float st[2] = {0.f, 0.f};
        #pragma unroll
        for (int e = 0; e < 16; e++) { st[0] += q[e]; st[1] += q[e]*q[e]; }
        warp_reduce<2>(st);
        {
            float mu   = st[0] * (1.f / DD);
            float var  = st[1] * (1.f / DD) - mu * mu;
            float rstd = rsqrtf(var + 1e-6f);
            #pragma unroll
            for (int e = 0; e < 16; e++)
                q[e] = tanhf((q[e] - mu) * rstd * gmv[e] + btv[e]);
        }
        // raw (clipped)
        float rv[16];
        #pragma unroll
        for (int j = 0; j < 4; j++) {
            float4 r4 = *(const float4*)(raw + (size_t)n * DD + lane * 4 + j * 128);
            rv[j*4+0]=clipf(r4.x,-50.f,50.f); rv[j*4+1]=clipf(r4.y,-50.f,50.f);
            rv[j*4+2]=clipf(r4.z,-50.f,50.f); rv[j*4+3]=clipf(r4.w,-50.f,50.f);
        }
        // ---- prototypes: load ONCE into registers ----
        float p[KK][16];
        #pragma unroll
        for (int k = 0; k < KK; k++) {
            const float* pr = proto + ((size_t)n * KK + k) * DD;
            #pragma unroll
            for (int j = 0; j < 4; j++) {
                float4 p4 = *(const float4*)(pr + lane * 4 + j * 128);
                p[k][j*4+0]=p4.x; p[k][j*4+1]=p4.y; p[k][j*4+2]=p4.z; p[k][j*4+3]=p4.w;
            }
        }
        // norms + dots (clipped view of p)
        float part[11];
        {
            float qss = 0.f;
            #pragma unroll
            for (int e = 0; e < 16; e++) qss += q[e]*q[e];
            part[0] = qss;
        }
        #pragma unroll
        for (int k = 0; k < KK; k++) {
            float pss = 0.f, pdot = 0.f;
            #pragma unroll
            for (int e = 0; e < 16; e++) {
                float ps = clipf(p[k][e], -20.f, 20.f);
                pss  = fmaf(ps, ps, pss);
                pdot = fmaf(ps, q[e], pdot);
            }
            part[1 + k] = pss;
            part[6 + k] = pdot;
        }
        warp_reduce<11>(part);

        float qn = fmaxf(sqrtf(part[0]), 1e-6f);
        float sim[KK], mx = -1e30f;
        #pragma unroll
        for (int k = 0; k < KK; k++) {
            float s = part[6 + k] / (qn * fmaxf(sqrtf(part[1 + k]), 1e-6f));
            s = clipf(s, -15.f, 15.f) / temp;
            sim[k] = s; mx = fmaxf(mx, s);
        }
        float denom = 0.f, attn[KK];
        #pragma unroll
        for (int k = 0; k < KK; k++) { attn[k] = expf(sim[k] - mx); denom += attn[k]; }
        float inv = 1.f / denom;
        #pragma unroll
        for (int k = 0; k < KK; k++) attn[k] = clipf(attn[k] * inv, 0.f, 1.f);

        // candidate from register-resident (unclipped) protos, clip +-5
        float cand[16];
        #pragma unroll
        for (int e = 0; e < 16; e++) {
            float cc = attn[0] * p[0][e];
            #pragma unroll
            for (int k = 1; k < KK; k++) cc = fmaf(attn[k], p[k][e], cc);
            cand[e] = clipf(cc, -5.f, 5.f);
        }

        // gate
        float gd[1] = {0.f};
        #pragma unroll
        for (int e = 0; e < 16; e++) {
            gd[0] += wg0[e] * clipf(rv[e],  -30.f, 30.f);
            gd[0] += wg1[e] * clipf(cand[e],-30.f, 30.f);
        }
        {
            float4 t4 = *(const float4*)(timeenc + (size_t)n * TT + lane * 4);
            gd[0] += wg2[0]*clipf(t4.x,-30.f,30.f) + wg2[1]*clipf(t4.y,-30.f,30.f)
                   + wg2[2]*clipf(t4.z,-30.f,30.f) + wg2[3]*clipf(t4.w,-30.f,30.f);
        }
        warp_reduce<1>(gd);
        float gl = clipf(gd[0] + bgv, -10.f, 10.f);
        float g  = 1.f / (1.f + expf(-gl));

        // residual + final LN
        float u[16], st2[2] = {0.f, 0.f};
        #pragma unroll
        for (int e = 0; e < 16; e++) {
            u[e] = 0.8f * rv[e] + 0.2f * ((1.f - g) * rv[e] + g * cand[e]);
            st2[0] += u[e]; st2[1] += u[e]*u[e];
        }
        warp_reduce<2>(st2);
        float mu   = st2[0] * (1.f / DD);
        float var  = st2[1] * (1.f / DD) - mu * mu;
        float rstd = rsqrtf(var + 1e-6f);
        #pragma unroll
        for (int j = 0; j < 4; j++) {
            float4 o;
            o.x = clipf((u[j*4+0]-mu)*rstd*gmv[j*4+0]+btv[j*4+0], -10.f, 10.f);
            o.y = clipf((u[j*4+1]-mu)*rstd*gmv[j*4+1]+btv[j*4+1], -10.f, 10.f);
            o.z = clipf((u[j*4+2]-mu)*rstd*gmv[j*4+2]+btv[j*4+2], -10.f, 10.f);
            o.w = clipf((u[j*4+3]-mu)*rstd*gmv[j*4+3]+btv[j*4+3], -10.f, 10.f);
            *(float4*)(out + (size_t)n * DD + lane * 4 + j * 128) = o;
        }
    }
}

// ---------------------------------------------------------------------------
extern "C" void kernel_launch(void* const* d_in, const int* in_sizes, int n_in,
                              void* d_out, int out_size) {
    const float* raw   = (const float*)d_in[0];
    // d_in[1] = node_features (unused by reference)
    const float* edge  = (const float*)d_in[2];
    const float* timee = (const float*)d_in[3];
    const float* proto = (const float*)d_in[4];
    const float* Wq    = (const float*)d_in[5];
    const float* bq    = (const float*)d_in[6];
    const float* Wg    = (const float*)d_in[7];
    const float* bg    = (const float*)d_in[8];
    const float* gamma = (const float*)d_in[9];
    const float* beta  = (const float*)d_in[10];
    const float* temp  = (const float*)d_in[11];
    float* out = (float*)d_out;

    cudaFuncSetAttribute(fused_kernel, cudaFuncAttributeMaxDynamicSharedMemorySize, SMEM_TOTAL);

    convert_wq<<<(DD * KTOT + 255) / 256, 256>>>(Wq);
    fused_kernel<<<N_ROWS / BM, 256, SMEM_TOTAL>>>(raw, edge, timee, proto, bq,
                                                   Wg, bg, gamma, beta, temp, out);
}